// round 13
// baseline (speedup 1.0000x reference)
#include <cuda_runtime.h>
#include <cuda_bf16.h>
#include <cuda_fp16.h>
#include <cstdint>
#include <math.h>

#define BATCH 1024
#define IN_F  512
#define OUT_F 512
#define NC    35        // raw spline coefficients per (o,i)
#define ROWQ  41        // slots per (i,o) row: 40 segments + bw in slot 40
#define OT    16        // outputs per block
#define ICH   32        // input features per block
#define NBI   (IN_F/ICH)
#define BT    512       // batches per block
#define C01_BYTES (OT * ROWQ * 8)      // 5248
#define C23_BYTES (OT * ROWQ * 4)      // 2624
#define SCX_BYTES (BT * 8)             // 4096
#define TOT_BYTES (C01_BYTES + C23_BYTES + SCX_BYTES)
#define RB    32        // table rows per prep_cub block
#define WST   37        // smem weight row stride (floats)

// ---------------- scratch (device globals; no allocation) ----------------
__device__ float2  g_c01[(size_t)IN_F * OUT_F * ROWQ];  // (c0,c1) fp32
__device__ __half2 g_c23[(size_t)IN_F * OUT_F * ROWQ];  // (c2,c3) fp16
__device__ float2  g_scx[IN_F * BATCH];                 // [i][b] (sc, silu(x))

// ---------------- P1: smem-staged rows; coalesced reads AND writes ----------------
__global__ __launch_bounds__(256) void prep_cub(const float* __restrict__ sw,
                                                const float* __restrict__ scaler,
                                                const int*   __restrict__ mask,
                                                const float* __restrict__ bwp) {
    __shared__ float s_w[RB * WST];
    __shared__ float s_scal[RB];
    __shared__ int   s_msk[RB];
    __shared__ float s_bw[RB];

    const int io0 = blockIdx.x * RB;     // io = i*OUT_F + o
    const int tid = threadIdx.x;

    #pragma unroll
    for (int k = 0; k < 5; k++) {
        const int idx = tid + k * 256;               // RB*NC = 1120
        if (idx < RB * NC) {
            const int r = idx / NC;
            const int c = idx - r * NC;
            const int io = io0 + r;
            const int i  = io >> 9;
            const int o  = io & (OUT_F - 1);
            s_w[r * WST + c] = sw[(size_t)(o * IN_F + i) * NC + c];
        }
    }
    if (tid < RB) {
        const int io = io0 + tid;
        const int i  = io >> 9;
        const int o  = io & (OUT_F - 1);
        const int oi = o * IN_F + i;
        s_scal[tid] = scaler[oi];
        s_msk[tid]  = mask[oi];
        s_bw[tid]   = bwp[oi];
    }
    __syncthreads();

    #pragma unroll
    for (int k = 0; k < 6; k++) {
        const int idx = tid + k * 256;               // RB*ROWQ = 1312
        if (idx >= RB * ROWQ) break;
        const int r = idx / ROWQ;
        const int m = idx - r * ROWQ;                // 0..40
        const float s  = s_scal[r];
        const bool  dm = (s_msk[r] != 0);
        const float* wr = &s_w[r * WST];

        float4 v;
        if (m == 40) {
            v = make_float4(s_bw[r], 0.f, 0.f, 0.f);
        } else if (dm) {
            const float s6 = s * (1.f / 6.f);
            const float ys = (wr[0]  + 4.f * wr[1]  + wr[2])  * s6;
            const float ye = (wr[32] + 4.f * wr[33] + wr[34]) * s6;
            const float a  = (ye - ys) * 0.5f;       // dx = 2
            const float b0 = ys + a;                 // b = ys - a*gmin
            v = make_float4(fmaf(a, (float)(m - 20) * 0.0625f, b0),
                            a * 0.0625f, 0.f, 0.f);
        } else if (m == 0 || m == 39) {
            v = make_float4(0.f, 0.f, 0.f, 0.f);
        } else {
            const int cc = m - 4;
            const float v0 = (cc     >= 0) ? wr[cc]     * s : 0.f;
            const float v1 = (cc + 1 >= 0 && cc + 1 <= 34) ? wr[cc + 1] * s : 0.f;
            const float v2 = (cc + 2 >= 0 && cc + 2 <= 34) ? wr[cc + 2] * s : 0.f;
            const float v3 = (cc + 3 <= 34) ? wr[cc + 3] * s : 0.f;
            v.x = (v0 + 4.f * v1 + v2) * (1.f / 6.f);
            v.y = (v2 - v0) * 0.5f;
            v.z = (v0 + v2) * 0.5f - v1;
            v.w = (3.f * (v1 - v2) + (v3 - v0)) * (1.f / 6.f);
        }
        const size_t gidx = (size_t)io0 * ROWQ + idx;
        g_c01[gidx] = make_float2(v.x, v.y);
        g_c23[gidx] = __floats2half2_rn(v.z, v.w);
    }
}

// ---------------- P2: (sc, silu) per (b,i) + zero out ----------------
__global__ void prep_bz(const float* __restrict__ x, float* __restrict__ out) {
    const int n = blockIdx.x * 256 + threadIdx.x;   // n = i*1024 + b
    const int i = n >> 10;
    const int b = n & 1023;
    const float xv = x[b * IN_F + i];
    g_scx[n] = make_float2(fmaf(xv, 16.f, 19.f), xv / (1.f + expf(-xv)));
    out[n]  = 0.f;                                  // BATCH*OUT_F == IN_F*BATCH
}

// ---------------- TMA bulk + mbarrier helpers ----------------
__device__ __forceinline__ unsigned smem_u32(const void* p) {
    return (unsigned)__cvta_generic_to_shared(p);
}
__device__ __forceinline__ void bulk_g2s(void* dst_smem, const void* src_gmem,
                                         unsigned bytes, unsigned mbar) {
    asm volatile(
        "cp.async.bulk.shared::cluster.global.mbarrier::complete_tx::bytes "
        "[%0], [%1], %2, [%3];\n"
        :: "r"(smem_u32(dst_smem)), "l"(src_gmem), "r"(bytes), "r"(mbar) : "memory");
}
#define MBAR_INIT(addr, cnt) \
    asm volatile("mbarrier.init.shared.b64 [%0], %1;" :: "r"(addr), "r"(cnt) : "memory")
#define MBAR_EXPECT_TX(addr, bytes) \
    asm volatile("mbarrier.arrive.expect_tx.shared.b64 _, [%0], %1;" \
                 :: "r"(addr), "r"(bytes) : "memory")
#define MBAR_WAIT(addr, parity) do {                                              \
    unsigned _m = (addr); unsigned _p = (parity); unsigned _done;                 \
    asm volatile("{\n\t.reg .pred p;\n\t"                                         \
        "mbarrier.try_wait.parity.acquire.cta.shared::cta.b64 p, [%1], %2;\n\t"   \
        "selp.b32 %0, 1, 0, p;\n\t}"                                              \
        : "=r"(_done) : "r"(_m), "r"(_p) : "memory");                             \
    if (!_done) {                                                                 \
        asm volatile("{\n\t.reg .pred P1;\n\t"                                    \
            "W1_%=:\n\t"                                                          \
            "mbarrier.try_wait.parity.acquire.cta.shared::cta.b64 P1, [%0], %1, 0x989680;\n\t" \
            "@P1 bra.uni W2_%=;\n\t"                                              \
            "bra.uni W1_%=;\n\t"                                                  \
            "W2_%=:\n\t}"                                                         \
            :: "r"(_m), "r"(_p) : "memory");                                      \
    }                                                                             \
} while (0)

// ---------------- main: TMA-staged, double-buffered evaluation ----------------
__global__ __launch_bounds__(512, 2) void main_k(float* __restrict__ out) {
    __shared__ __align__(16) float2  s_c01[2][OT * ROWQ];
    __shared__ __align__(16) __half2 s_c23[2][OT * ROWQ];
    __shared__ __align__(16) float2  s_scx[2][BT];
    __shared__ __align__(8)  unsigned long long s_bar[2];

    const int o0   = blockIdx.x * OT;
    const int boff = blockIdx.y * BT;
    const int i0   = blockIdx.z * ICH;
    const int tid  = threadIdx.x;
    const int w    = tid >> 5;
    const int lane = tid & 31;
    const int ol   = lane & 7;
    const int bg   = lane >> 3;
    const int tb   = w * 32 + bg * 8;

    const unsigned bar0 = smem_u32(&s_bar[0]);
    const unsigned bar1 = smem_u32(&s_bar[1]);

    float acc0[8], acc1[8];
    #pragma unroll
    for (int j = 0; j < 8; j++) { acc0[j] = 0.f; acc1[j] = 0.f; }

    if (tid == 0) { MBAR_INIT(bar0, 1); MBAR_INIT(bar1, 1); }
    __syncthreads();

    auto issue = [&](int ii, int buf, unsigned bar) {
        const int i = i0 + ii;
        const size_t row = (size_t)i * OUT_F + o0;
        MBAR_EXPECT_TX(bar, TOT_BYTES);
        bulk_g2s(&s_c01[buf][0], g_c01 + row * ROWQ, C01_BYTES, bar);
        bulk_g2s(&s_c23[buf][0], g_c23 + row * ROWQ, C23_BYTES, bar);
        bulk_g2s(&s_scx[buf][0], g_scx + i * BATCH + boff, SCX_BYTES, bar);
    };

    if (tid == 0) issue(0, 0, bar0);
    int ph0 = 0, ph1 = 0;

    for (int ii = 0; ii < ICH; ii++) {
        const int buf = ii & 1;
        if (buf == 0) { MBAR_WAIT(bar0, ph0); ph0 ^= 1; }
        else          { MBAR_WAIT(bar1, ph1); ph1 ^= 1; }

        if (tid == 0 && ii + 1 < ICH)
            issue(ii + 1, buf ^ 1, (buf == 0) ? bar1 : bar0);

        const float2*  C01 = s_c01[buf];
        const __half2* C23 = s_c23[buf];
        const float bw0 = C01[ol * ROWQ + 40].x;
        const float bw1 = C01[(ol + 8) * ROWQ + 40].x;

        const float4* scx4 = (const float4*)&s_scx[buf][tb];
        float4 p[4];
        #pragma unroll
        for (int q = 0; q < 4; q++) p[q] = scx4[q];   // (sc,sx,sc,sx)

        #pragma unroll
        for (int j = 0; j < 8; j++) {
            const float sc = (j & 1) ? p[j >> 1].z : p[j >> 1].x;
            const float sx = (j & 1) ? p[j >> 1].w : p[j >> 1].y;
            const float sgc = fminf(fmaxf(floorf(sc), -1.f), 38.f);
            const float u  = sc - sgc;
            const int   m  = (int)sgc + 1;
            const int r0 = ol * ROWQ + m;
            const int r1 = (ol + 8) * ROWQ + m;
            const float2 a0 = C01[r0];
            const float2 a1 = C01[r1];
            const float2 q0 = __half22float2(C23[r0]);
            const float2 q1 = __half22float2(C23[r1]);
            acc0[j] += fmaf(bw0, sx, fmaf(fmaf(fmaf(q0.y, u, q0.x), u, a0.y), u, a0.x));
            acc1[j] += fmaf(bw1, sx, fmaf(fmaf(fmaf(q1.y, u, q1.x), u, a1.y), u, a1.x));
        }

        __syncthreads();   // all threads done reading buf -> it may be refilled
    }

    #pragma unroll
    for (int j = 0; j < 8; j++) {
        const int b = boff + tb + j;
        atomicAdd(&out[b * OUT_F + o0 + ol],     acc0[j]);
        atomicAdd(&out[b * OUT_F + o0 + ol + 8], acc1[j]);
    }
}

// ---------------- launch ----------------
extern "C" void kernel_launch(void* const* d_in, const int* in_sizes, int n_in,
                              void* d_out, int out_size) {
    const float* x      = (const float*)d_in[0];  // (1024, 512)
    const float* bw     = (const float*)d_in[1];  // (512, 512)
    const float* sw     = (const float*)d_in[2];  // (512, 512, 35)
    const float* scaler = (const float*)d_in[3];  // (512, 512)
    // d_in[4] = grid (uniform; derived analytically)
    const int*   mask   = (const int*)d_in[5];    // (512, 512)
    float* out = (float*)d_out;                   // (1024, 512)

    prep_cub<<<(IN_F * OUT_F) / RB, 256>>>(sw, scaler, mask, bw);
    prep_bz<<<(IN_F * BATCH) / 256, 256>>>(x, out);
    main_k<<<dim3(OUT_F / OT, BATCH / BT, NBI), 512>>>(out);
}

// round 14
// speedup vs baseline: 1.2834x; 1.2834x over previous
#include <cuda_runtime.h>
#include <cuda_bf16.h>
#include <cstdint>
#include <math.h>

#define BATCH 1024
#define IN_F  512
#define OUT_F 512
#define NC    35        // raw spline coefficients per (o,i)
#define ROWQ  41        // float4 slots per (i,o) row: 40 segments + bw in slot 40
#define OT    16        // outputs per block
#define ICH   32        // input features per block
#define NBI   (IN_F/ICH)
#define BT    512       // batches per block
#define C_BYTES  (OT * ROWQ * 16)      // 10496
#define SCX_BYTES (BT * 8)             // 4096
#define TOT_BYTES (C_BYTES + SCX_BYTES)
#define RB    32        // table rows (io values) per prep_cub block
#define WST   37        // smem weight row stride (floats)

// ---------------- scratch (device globals; no allocation) ----------------
__device__ float4 g_cub[(size_t)IN_F * OUT_F * ROWQ];   // [i][o][41] coeffs + bw
__device__ float2 g_scx[IN_F * BATCH];                  // [i][b] (sc, silu(x))

// ---------------- P1: smem-staged rows; 8 threads/row, no div/mod ----------------
__global__ __launch_bounds__(256) void prep_cub(const float* __restrict__ sw,
                                                const float* __restrict__ scaler,
                                                const int*   __restrict__ mask,
                                                const float* __restrict__ bwp) {
    __shared__ float s_w[RB * WST];      // raw weights, stride-37
    __shared__ float s_scal[RB];
    __shared__ int   s_msk[RB];
    __shared__ float s_bw[RB];

    const int io0 = blockIdx.x * RB;     // first table row (io = i*OUT_F + o)
    const int tid = threadIdx.x;

    // ---- stage: coalesced within each 140B row ----
    #pragma unroll
    for (int k = 0; k < 5; k++) {
        const int idx = tid + k * 256;               // RB*NC = 1120
        if (idx < RB * NC) {
            const int r = idx / NC;
            const int c = idx - r * NC;
            const int io = io0 + r;
            const int i  = io >> 9;
            const int o  = io & (OUT_F - 1);
            s_w[r * WST + c] = sw[(size_t)(o * IN_F + i) * NC + c];
        }
    }
    if (tid < RB) {
        const int io = io0 + tid;
        const int i  = io >> 9;
        const int o  = io & (OUT_F - 1);
        const int oi = o * IN_F + i;
        s_scal[tid] = scaler[oi];
        s_msk[tid]  = mask[oi];
        s_bw[tid]   = bwp[oi];
    }
    __syncthreads();

    // ---- build: 8 threads per row, slot stride 8 ----
    const int r  = tid >> 3;             // 0..31
    const int s0 = tid & 7;              // 0..7
    const float s  = s_scal[r];
    const bool  dm = (s_msk[r] != 0);
    const float bwv = s_bw[r];
    const float* wr = &s_w[r * WST];

    // row-level linear fallback constants (used only if dm)
    const float s6 = s * (1.f / 6.f);
    const float ys = (wr[0]  + 4.f * wr[1]  + wr[2])  * s6;
    const float ye = (wr[32] + 4.f * wr[33] + wr[34]) * s6;
    const float a  = (ye - ys) * 0.5f;   // dx = 2
    const float b0 = ys + a;             // b = ys - a*gmin

    float4* dst = g_cub + (size_t)(io0 + r) * ROWQ;

    #pragma unroll
    for (int m = 0; m <= 40; m += 8) {
        const int mm = m + s0;
        if (mm > 40) break;
        float4 v;
        if (mm == 40) {
            v = make_float4(bwv, 0.f, 0.f, 0.f);
        } else if (dm) {
            v = make_float4(fmaf(a, (float)(mm - 20) * 0.0625f, b0),
                            a * 0.0625f, 0.f, 0.f);
        } else if (mm == 0 || mm == 39) {
            v = make_float4(0.f, 0.f, 0.f, 0.f);
        } else {
            const int cc = mm - 4;
            const float v0 = (cc     >= 0) ? wr[cc]     * s : 0.f;
            const float v1 = (cc + 1 >= 0 && cc + 1 <= 34) ? wr[cc + 1] * s : 0.f;
            const float v2 = (cc + 2 >= 0 && cc + 2 <= 34) ? wr[cc + 2] * s : 0.f;
            const float v3 = (cc + 3 <= 34) ? wr[cc + 3] * s : 0.f;
            v.x = (v0 + 4.f * v1 + v2) * (1.f / 6.f);
            v.y = (v2 - v0) * 0.5f;
            v.z = (v0 + v2) * 0.5f - v1;
            v.w = (3.f * (v1 - v2) + (v3 - v0)) * (1.f / 6.f);
        }
        dst[mm] = v;
    }
}

// ---------------- P2: (sc, silu) per (b,i) + zero out ----------------
__global__ void prep_bz(const float* __restrict__ x, float* __restrict__ out) {
    const int n = blockIdx.x * 256 + threadIdx.x;   // n = i*1024 + b
    const int i = n >> 10;
    const int b = n & 1023;
    const float xv = x[b * IN_F + i];
    g_scx[n] = make_float2(fmaf(xv, 16.f, 19.f), xv / (1.f + expf(-xv)));
    out[n]  = 0.f;                                  // BATCH*OUT_F == IN_F*BATCH
}

// ---------------- TMA bulk + mbarrier helpers ----------------
__device__ __forceinline__ unsigned smem_u32(const void* p) {
    return (unsigned)__cvta_generic_to_shared(p);
}
__device__ __forceinline__ void bulk_g2s(void* dst_smem, const void* src_gmem,
                                         unsigned bytes, unsigned mbar) {
    asm volatile(
        "cp.async.bulk.shared::cluster.global.mbarrier::complete_tx::bytes "
        "[%0], [%1], %2, [%3];\n"
        :: "r"(smem_u32(dst_smem)), "l"(src_gmem), "r"(bytes), "r"(mbar) : "memory");
}
#define MBAR_INIT(addr, cnt) \
    asm volatile("mbarrier.init.shared.b64 [%0], %1;" :: "r"(addr), "r"(cnt) : "memory")
#define MBAR_EXPECT_TX(addr, bytes) \
    asm volatile("mbarrier.arrive.expect_tx.shared.b64 _, [%0], %1;" \
                 :: "r"(addr), "r"(bytes) : "memory")
#define MBAR_WAIT(addr, parity) do {                                              \
    unsigned _m = (addr); unsigned _p = (parity); unsigned _done;                 \
    asm volatile("{\n\t.reg .pred p;\n\t"                                         \
        "mbarrier.try_wait.parity.acquire.cta.shared::cta.b64 p, [%1], %2;\n\t"   \
        "selp.b32 %0, 1, 0, p;\n\t}"                                              \
        : "=r"(_done) : "r"(_m), "r"(_p) : "memory");                             \
    if (!_done) {                                                                 \
        asm volatile("{\n\t.reg .pred P1;\n\t"                                    \
            "W1_%=:\n\t"                                                          \
            "mbarrier.try_wait.parity.acquire.cta.shared::cta.b64 P1, [%0], %1, 0x989680;\n\t" \
            "@P1 bra.uni W2_%=;\n\t"                                              \
            "bra.uni W1_%=;\n\t"                                                  \
            "W2_%=:\n\t}"                                                         \
            :: "r"(_m), "r"(_p) : "memory");                                      \
    }                                                                             \
} while (0)

// ---------------- main: TMA-staged, double-buffered evaluation (R12) ----------------
__global__ __launch_bounds__(512, 2) void main_k(float* __restrict__ out) {
    __shared__ __align__(16) float4 s_C[2][OT * ROWQ];   // stride-41 rows
    __shared__ __align__(16) float2 s_scx[2][BT];
    __shared__ __align__(8)  unsigned long long s_bar[2];

    const int o0   = blockIdx.x * OT;
    const int boff = blockIdx.y * BT;
    const int i0   = blockIdx.z * ICH;
    const int tid  = threadIdx.x;
    const int w    = tid >> 5;
    const int lane = tid & 31;
    const int ol   = lane & 7;
    const int bg   = lane >> 3;
    const int tb   = w * 32 + bg * 8;        // thread's first b within block tile

    const unsigned bar0 = smem_u32(&s_bar[0]);
    const unsigned bar1 = smem_u32(&s_bar[1]);

    float acc0[8], acc1[8];
    #pragma unroll
    for (int j = 0; j < 8; j++) { acc0[j] = 0.f; acc1[j] = 0.f; }

    if (tid == 0) { MBAR_INIT(bar0, 1); MBAR_INIT(bar1, 1); }
    __syncthreads();

    auto issue = [&](int ii, int buf, unsigned bar) {
        const int i = i0 + ii;
        MBAR_EXPECT_TX(bar, TOT_BYTES);
        bulk_g2s(&s_C[buf][0], g_cub + ((size_t)i * OUT_F + o0) * ROWQ, C_BYTES, bar);
        bulk_g2s(&s_scx[buf][0], g_scx + i * BATCH + boff, SCX_BYTES, bar);
    };

    if (tid == 0) issue(0, 0, bar0);
    int ph0 = 0, ph1 = 0;

    for (int ii = 0; ii < ICH; ii++) {
        const int buf = ii & 1;
        if (buf == 0) { MBAR_WAIT(bar0, ph0); ph0 ^= 1; }
        else          { MBAR_WAIT(bar1, ph1); ph1 ^= 1; }

        if (tid == 0 && ii + 1 < ICH)
            issue(ii + 1, buf ^ 1, (buf == 0) ? bar1 : bar0);

        const float4* Cc = s_C[buf];
        const float bw0 = ((const float*)&Cc[ol * ROWQ + 40])[0];
        const float bw1 = ((const float*)&Cc[(ol + 8) * ROWQ + 40])[0];

        const float4* scx4 = (const float4*)&s_scx[buf][tb];
        float4 p[4];
        #pragma unroll
        for (int q = 0; q < 4; q++) p[q] = scx4[q];   // (sc,sx,sc,sx)

        #pragma unroll
        for (int j = 0; j < 8; j++) {
            const float sc = (j & 1) ? p[j >> 1].z : p[j >> 1].x;
            const float sx = (j & 1) ? p[j >> 1].w : p[j >> 1].y;
            const float sgc = fminf(fmaxf(floorf(sc), -1.f), 38.f);
            const float u  = sc - sgc;
            const int   m  = (int)sgc + 1;
            const float4 c0 = Cc[ol * ROWQ + m];
            const float4 c1 = Cc[(ol + 8) * ROWQ + m];
            acc0[j] += fmaf(bw0, sx, fmaf(fmaf(fmaf(c0.w, u, c0.z), u, c0.y), u, c0.x));
            acc1[j] += fmaf(bw1, sx, fmaf(fmaf(fmaf(c1.w, u, c1.z), u, c1.y), u, c1.x));
        }

        __syncthreads();   // all threads done reading buf -> it may be refilled
    }

    #pragma unroll
    for (int j = 0; j < 8; j++) {
        const int b = boff + tb + j;
        atomicAdd(&out[b * OUT_F + o0 + ol],     acc0[j]);
        atomicAdd(&out[b * OUT_F + o0 + ol + 8], acc1[j]);
    }
}

// ---------------- launch ----------------
extern "C" void kernel_launch(void* const* d_in, const int* in_sizes, int n_in,
                              void* d_out, int out_size) {
    const float* x      = (const float*)d_in[0];  // (1024, 512)
    const float* bw     = (const float*)d_in[1];  // (512, 512)
    const float* sw     = (const float*)d_in[2];  // (512, 512, 35)
    const float* scaler = (const float*)d_in[3];  // (512, 512)
    // d_in[4] = grid (uniform; derived analytically)
    const int*   mask   = (const int*)d_in[5];    // (512, 512)
    float* out = (float*)d_out;                   // (1024, 512)

    prep_cub<<<(IN_F * OUT_F) / RB, 256>>>(sw, scaler, mask, bw);
    prep_bz<<<(IN_F * BATCH) / 256, 256>>>(x, out);
    main_k<<<dim3(OUT_F / OT, BATCH / BT, NBI), 512>>>(out);
}

// round 15
// speedup vs baseline: 1.2883x; 1.0038x over previous
#include <cuda_runtime.h>
#include <cuda_bf16.h>
#include <cstdint>
#include <math.h>

#define BATCH 1024
#define IN_F  512
#define OUT_F 512
#define NC    35        // raw spline coefficients per (o,i)
#define ROWQ  41        // float4 slots per (i,o) row: 40 segments + bw in slot 40
#define OT    16        // outputs per block
#define ICH   32        // input features per block
#define NBI   (IN_F/ICH)
#define BT    512       // batches per block
#define C_BYTES  (OT * ROWQ * 16)      // 10496
#define SCX_BYTES (BT * 8)             // 4096
#define TOT_BYTES (C_BYTES + SCX_BYTES)
#define RB    32        // table rows (io values) per prep_cub block
#define WST   37        // smem weight row stride (floats)
#define NSTG  3         // TMA pipeline stages

// ---------------- scratch (device globals; no allocation) ----------------
__device__ float4 g_cub[(size_t)IN_F * OUT_F * ROWQ];   // [i][o][41] coeffs + bw
__device__ float2 g_scx[IN_F * BATCH];                  // [i][b] (sc, silu(x))

// ---------------- P1: smem-staged rows; 8 threads/row, no div/mod ----------------
__global__ __launch_bounds__(256) void prep_cub(const float* __restrict__ sw,
                                                const float* __restrict__ scaler,
                                                const int*   __restrict__ mask,
                                                const float* __restrict__ bwp) {
    __shared__ float s_w[RB * WST];      // raw weights, stride-37
    __shared__ float s_scal[RB];
    __shared__ int   s_msk[RB];
    __shared__ float s_bw[RB];

    const int io0 = blockIdx.x * RB;     // first table row (io = i*OUT_F + o)
    const int tid = threadIdx.x;

    #pragma unroll
    for (int k = 0; k < 5; k++) {
        const int idx = tid + k * 256;               // RB*NC = 1120
        if (idx < RB * NC) {
            const int r = idx / NC;
            const int c = idx - r * NC;
            const int io = io0 + r;
            const int i  = io >> 9;
            const int o  = io & (OUT_F - 1);
            s_w[r * WST + c] = sw[(size_t)(o * IN_F + i) * NC + c];
        }
    }
    if (tid < RB) {
        const int io = io0 + tid;
        const int i  = io >> 9;
        const int o  = io & (OUT_F - 1);
        const int oi = o * IN_F + i;
        s_scal[tid] = scaler[oi];
        s_msk[tid]  = mask[oi];
        s_bw[tid]   = bwp[oi];
    }
    __syncthreads();

    const int r  = tid >> 3;             // 0..31
    const int s0 = tid & 7;              // 0..7
    const float s  = s_scal[r];
    const bool  dm = (s_msk[r] != 0);
    const float bwv = s_bw[r];
    const float* wr = &s_w[r * WST];

    const float s6 = s * (1.f / 6.f);
    const float ys = (wr[0]  + 4.f * wr[1]  + wr[2])  * s6;
    const float ye = (wr[32] + 4.f * wr[33] + wr[34]) * s6;
    const float a  = (ye - ys) * 0.5f;   // dx = 2
    const float b0 = ys + a;             // b = ys - a*gmin

    float4* dst = g_cub + (size_t)(io0 + r) * ROWQ;

    #pragma unroll
    for (int m = 0; m <= 40; m += 8) {
        const int mm = m + s0;
        if (mm > 40) break;
        float4 v;
        if (mm == 40) {
            v = make_float4(bwv, 0.f, 0.f, 0.f);
        } else if (dm) {
            v = make_float4(fmaf(a, (float)(mm - 20) * 0.0625f, b0),
                            a * 0.0625f, 0.f, 0.f);
        } else if (mm == 0 || mm == 39) {
            v = make_float4(0.f, 0.f, 0.f, 0.f);
        } else {
            const int cc = mm - 4;
            const float v0 = (cc     >= 0) ? wr[cc]     * s : 0.f;
            const float v1 = (cc + 1 >= 0 && cc + 1 <= 34) ? wr[cc + 1] * s : 0.f;
            const float v2 = (cc + 2 >= 0 && cc + 2 <= 34) ? wr[cc + 2] * s : 0.f;
            const float v3 = (cc + 3 <= 34) ? wr[cc + 3] * s : 0.f;
            v.x = (v0 + 4.f * v1 + v2) * (1.f / 6.f);
            v.y = (v2 - v0) * 0.5f;
            v.z = (v0 + v2) * 0.5f - v1;
            v.w = (3.f * (v1 - v2) + (v3 - v0)) * (1.f / 6.f);
        }
        dst[mm] = v;
    }
}

// ---------------- P2: (sc, silu) per (b,i) + zero out ----------------
__global__ void prep_bz(const float* __restrict__ x, float* __restrict__ out) {
    const int n = blockIdx.x * 256 + threadIdx.x;   // n = i*1024 + b
    const int i = n >> 10;
    const int b = n & 1023;
    const float xv = x[b * IN_F + i];
    g_scx[n] = make_float2(fmaf(xv, 16.f, 19.f), xv / (1.f + expf(-xv)));
    out[n]  = 0.f;                                  // BATCH*OUT_F == IN_F*BATCH
}

// ---------------- TMA bulk + mbarrier helpers ----------------
__device__ __forceinline__ unsigned smem_u32(const void* p) {
    return (unsigned)__cvta_generic_to_shared(p);
}
__device__ __forceinline__ void bulk_g2s(void* dst_smem, const void* src_gmem,
                                         unsigned bytes, unsigned mbar) {
    asm volatile(
        "cp.async.bulk.shared::cluster.global.mbarrier::complete_tx::bytes "
        "[%0], [%1], %2, [%3];\n"
        :: "r"(smem_u32(dst_smem)), "l"(src_gmem), "r"(bytes), "r"(mbar) : "memory");
}
#define MBAR_INIT(addr, cnt) \
    asm volatile("mbarrier.init.shared.b64 [%0], %1;" :: "r"(addr), "r"(cnt) : "memory")
#define MBAR_EXPECT_TX(addr, bytes) \
    asm volatile("mbarrier.arrive.expect_tx.shared.b64 _, [%0], %1;" \
                 :: "r"(addr), "r"(bytes) : "memory")
#define MBAR_WAIT(addr, parity) do {                                              \
    unsigned _m = (addr); unsigned _p = (parity); unsigned _done;                 \
    asm volatile("{\n\t.reg .pred p;\n\t"                                         \
        "mbarrier.try_wait.parity.acquire.cta.shared::cta.b64 p, [%1], %2;\n\t"   \
        "selp.b32 %0, 1, 0, p;\n\t}"                                              \
        : "=r"(_done) : "r"(_m), "r"(_p) : "memory");                             \
    if (!_done) {                                                                 \
        asm volatile("{\n\t.reg .pred P1;\n\t"                                    \
            "W1_%=:\n\t"                                                          \
            "mbarrier.try_wait.parity.acquire.cta.shared::cta.b64 P1, [%0], %1, 0x989680;\n\t" \
            "@P1 bra.uni W2_%=;\n\t"                                              \
            "bra.uni W1_%=;\n\t"                                                  \
            "W2_%=:\n\t}"                                                         \
            :: "r"(_m), "r"(_p) : "memory");                                      \
    }                                                                             \
} while (0)

// ---------------- main: 3-stage TMA ring, double-distance prefetch ----------------
__global__ __launch_bounds__(512, 2) void main_k(float* __restrict__ out) {
    __shared__ __align__(16) float4 s_C[NSTG][OT * ROWQ];   // stride-41 rows
    __shared__ __align__(16) float2 s_scx[NSTG][BT];
    __shared__ __align__(8)  unsigned long long s_bar[NSTG];

    const int o0   = blockIdx.x * OT;
    const int boff = blockIdx.y * BT;
    const int i0   = blockIdx.z * ICH;
    const int tid  = threadIdx.x;
    const int w    = tid >> 5;
    const int lane = tid & 31;
    const int ol   = lane & 7;
    const int bg   = lane >> 3;
    const int tb   = w * 32 + bg * 8;        // thread's first b within block tile

    float acc0[8], acc1[8];
    #pragma unroll
    for (int j = 0; j < 8; j++) { acc0[j] = 0.f; acc1[j] = 0.f; }

    if (tid == 0) {
        #pragma unroll
        for (int s = 0; s < NSTG; s++) MBAR_INIT(smem_u32(&s_bar[s]), 1);
    }
    __syncthreads();

    auto issue = [&](int ii, int stg) {
        const int i = i0 + ii;
        const unsigned bar = smem_u32(&s_bar[stg]);
        MBAR_EXPECT_TX(bar, TOT_BYTES);
        bulk_g2s(&s_C[stg][0], g_cub + ((size_t)i * OUT_F + o0) * ROWQ, C_BYTES, bar);
        bulk_g2s(&s_scx[stg][0], g_scx + i * BATCH + boff, SCX_BYTES, bar);
    };

    if (tid == 0) { issue(0, 0); issue(1, 1); }   // prefetch distance 2

    int cs = 0, cp = 0;        // consumer stage / phase
    int iss = 2;               // next issue stage

    for (int ii = 0; ii < ICH; ii++) {
        MBAR_WAIT(smem_u32(&s_bar[cs]), cp);

        if (tid == 0 && ii + 2 < ICH) {
            issue(ii + 2, iss);
            if (++iss == NSTG) iss = 0;
        }

        const float4* Cc = s_C[cs];
        const float bw0 = ((const float*)&Cc[ol * ROWQ + 40])[0];
        const float bw1 = ((const float*)&Cc[(ol + 8) * ROWQ + 40])[0];

        const float4* scx4 = (const float4*)&s_scx[cs][tb];
        float4 p[4];
        #pragma unroll
        for (int q = 0; q < 4; q++) p[q] = scx4[q];   // (sc,sx,sc,sx)

        #pragma unroll
        for (int j = 0; j < 8; j++) {
            const float sc = (j & 1) ? p[j >> 1].z : p[j >> 1].x;
            const float sx = (j & 1) ? p[j >> 1].w : p[j >> 1].y;
            const float sgc = fminf(fmaxf(floorf(sc), -1.f), 38.f);
            const float u  = sc - sgc;
            const int   m  = (int)sgc + 1;
            const float4 c0 = Cc[ol * ROWQ + m];
            const float4 c1 = Cc[(ol + 8) * ROWQ + m];
            acc0[j] += fmaf(bw0, sx, fmaf(fmaf(fmaf(c0.w, u, c0.z), u, c0.y), u, c0.x));
            acc1[j] += fmaf(bw1, sx, fmaf(fmaf(fmaf(c1.w, u, c1.z), u, c1.y), u, c1.x));
        }

        __syncthreads();   // all threads done with stage cs -> it may be refilled

        if (++cs == NSTG) { cs = 0; cp ^= 1; }
    }

    #pragma unroll
    for (int j = 0; j < 8; j++) {
        const int b = boff + tb + j;
        atomicAdd(&out[b * OUT_F + o0 + ol],     acc0[j]);
        atomicAdd(&out[b * OUT_F + o0 + ol + 8], acc1[j]);
    }
}

// ---------------- launch ----------------
extern "C" void kernel_launch(void* const* d_in, const int* in_sizes, int n_in,
                              void* d_out, int out_size) {
    const float* x      = (const float*)d_in[0];  // (1024, 512)
    const float* bw     = (const float*)d_in[1];  // (512, 512)
    const float* sw     = (const float*)d_in[2];  // (512, 512, 35)
    const float* scaler = (const float*)d_in[3];  // (512, 512)
    // d_in[4] = grid (uniform; derived analytically)
    const int*   mask   = (const int*)d_in[5];    // (512, 512)
    float* out = (float*)d_out;                   // (1024, 512)

    prep_cub<<<(IN_F * OUT_F) / RB, 256>>>(sw, scaler, mask, bw);
    prep_bz<<<(IN_F * BATCH) / 256, 256>>>(x, out);
    main_k<<<dim3(OUT_F / OT, BATCH / BT, NBI), 512>>>(out);
}

// round 16
// speedup vs baseline: 1.3822x; 1.0729x over previous
#include <cuda_runtime.h>
#include <cuda_bf16.h>
#include <cuda_fp16.h>
#include <cstdint>
#include <math.h>

#define BATCH 1024
#define IN_F  512
#define OUT_F 512
#define NC    35        // raw spline coefficients per (o,i)
#define ROWQ  41        // 16B slots per (i,opair) row: 40 segments + bw pair in slot 40
#define OT    16        // outputs per block
#define NPAIR 8         // output pairs per block (ol, ol+8)
#define ICH   32        // input features per block
#define NBI   (IN_F/ICH)
#define BT    512       // batches per block
#define C_BYTES  (NPAIR * ROWQ * 16)   // 5248
#define SCX_BYTES (BT * 8)             // 4096
#define TOT_BYTES (C_BYTES + SCX_BYTES)
#define RB    32        // table rows (io values) per prep_cub block
#define WST   37        // smem weight row stride (floats)
#define NSTG  3         // TMA pipeline stages

// ---------------- scratch (device globals; no allocation) ----------------
// g_pk[i][pair 0..255][slot 0..40] : 16B = {h2(d0,d1)A, h2(d2,d3)A, h2(d0,d1)B, h2(d2,d3)B}
// slot 40: {bwA fp32, 0, bwB fp32, 0}
__device__ uint4  g_pk[(size_t)IN_F * 256 * ROWQ];
__device__ float2 g_scx[IN_F * BATCH];                  // [i][b] (sc, silu(x))

// ---------------- P1: smem-staged rows; 8 threads/row; fp16 recentered coeffs ----------------
__global__ __launch_bounds__(256) void prep_cub(const float* __restrict__ sw,
                                                const float* __restrict__ scaler,
                                                const int*   __restrict__ mask,
                                                const float* __restrict__ bwp) {
    __shared__ float s_w[RB * WST];      // raw weights, stride-37
    __shared__ float s_scal[RB];
    __shared__ int   s_msk[RB];
    __shared__ float s_bw[RB];

    const int io0 = blockIdx.x * RB;     // first table row (io = i*OUT_F + o)
    const int tid = threadIdx.x;

    #pragma unroll
    for (int k = 0; k < 5; k++) {
        const int idx = tid + k * 256;               // RB*NC = 1120
        if (idx < RB * NC) {
            const int r = idx / NC;
            const int c = idx - r * NC;
            const int io = io0 + r;
            const int i  = io >> 9;
            const int o  = io & (OUT_F - 1);
            s_w[r * WST + c] = sw[(size_t)(o * IN_F + i) * NC + c];
        }
    }
    if (tid < RB) {
        const int io = io0 + tid;
        const int i  = io >> 9;
        const int o  = io & (OUT_F - 1);
        const int oi = o * IN_F + i;
        s_scal[tid] = scaler[oi];
        s_msk[tid]  = mask[oi];
        s_bw[tid]   = bwp[oi];
    }
    __syncthreads();

    const int r  = tid >> 3;             // 0..31
    const int s0 = tid & 7;              // 0..7
    const float s  = s_scal[r];
    const bool  dm = (s_msk[r] != 0);
    const float bwv = s_bw[r];
    const float* wr = &s_w[r * WST];

    const float s6 = s * (1.f / 6.f);
    const float ys = (wr[0]  + 4.f * wr[1]  + wr[2])  * s6;
    const float ye = (wr[32] + 4.f * wr[33] + wr[34]) * s6;
    const float a  = (ye - ys) * 0.5f;   // dx = 2
    const float b0 = ys + a;             // b = ys - a*gmin

    const int io = io0 + r;
    const int i  = io >> 9;
    const int o  = io & (OUT_F - 1);
    const int P  = i * 256 + ((o >> 4) << 3) + (o & 7);   // pair row
    const int hf = (o >> 3) & 1;                          // which half of the 16B slot
    uint2* dst = ((uint2*)g_pk) + (size_t)P * ROWQ * 2 + hf;

    #pragma unroll
    for (int m = 0; m <= 40; m += 8) {
        const int mm = m + s0;
        if (mm > 40) break;
        uint2 st;
        if (mm == 40) {
            st.x = __float_as_uint(bwv);
            st.y = 0u;
        } else {
            float4 v;
            if (dm) {
                v = make_float4(fmaf(a, (float)(mm - 20) * 0.0625f, b0),
                                a * 0.0625f, 0.f, 0.f);
            } else if (mm == 0 || mm == 39) {
                v = make_float4(0.f, 0.f, 0.f, 0.f);
            } else {
                const int cc = mm - 4;
                const float v0 = (cc     >= 0) ? wr[cc]     * s : 0.f;
                const float v1 = (cc + 1 >= 0 && cc + 1 <= 34) ? wr[cc + 1] * s : 0.f;
                const float v2 = (cc + 2 >= 0 && cc + 2 <= 34) ? wr[cc + 2] * s : 0.f;
                const float v3 = (cc + 3 <= 34) ? wr[cc + 3] * s : 0.f;
                v.x = (v0 + 4.f * v1 + v2) * (1.f / 6.f);
                v.y = (v2 - v0) * 0.5f;
                v.z = (v0 + v2) * 0.5f - v1;
                v.w = (3.f * (v1 - v2) + (v3 - v0)) * (1.f / 6.f);
            }
            // recenter at u = 0.5: t = u - 0.5
            const float d0 = v.x + 0.5f * v.y + 0.25f * v.z + 0.125f * v.w;
            const float d1 = v.y + v.z + 0.75f * v.w;
            const float d2 = v.z + 1.5f * v.w;
            const float d3 = v.w;
            const __half2 h01 = __floats2half2_rn(d0, d1);
            const __half2 h23 = __floats2half2_rn(d2, d3);
            st.x = *(const unsigned*)&h01;
            st.y = *(const unsigned*)&h23;
        }
        dst[mm * 2] = st;
    }
}

// ---------------- P2: (sc, silu) per (b,i) + zero out ----------------
__global__ void prep_bz(const float* __restrict__ x, float* __restrict__ out) {
    const int n = blockIdx.x * 256 + threadIdx.x;   // n = i*1024 + b
    const int i = n >> 10;
    const int b = n & 1023;
    const float xv = x[b * IN_F + i];
    g_scx[n] = make_float2(fmaf(xv, 16.f, 19.f), xv / (1.f + expf(-xv)));
    out[n]  = 0.f;                                  // BATCH*OUT_F == IN_F*BATCH
}

// ---------------- TMA bulk + mbarrier helpers ----------------
__device__ __forceinline__ unsigned smem_u32(const void* p) {
    return (unsigned)__cvta_generic_to_shared(p);
}
__device__ __forceinline__ void bulk_g2s(void* dst_smem, const void* src_gmem,
                                         unsigned bytes, unsigned mbar) {
    asm volatile(
        "cp.async.bulk.shared::cluster.global.mbarrier::complete_tx::bytes "
        "[%0], [%1], %2, [%3];\n"
        :: "r"(smem_u32(dst_smem)), "l"(src_gmem), "r"(bytes), "r"(mbar) : "memory");
}
#define MBAR_INIT(addr, cnt) \
    asm volatile("mbarrier.init.shared.b64 [%0], %1;" :: "r"(addr), "r"(cnt) : "memory")
#define MBAR_EXPECT_TX(addr, bytes) \
    asm volatile("mbarrier.arrive.expect_tx.shared.b64 _, [%0], %1;" \
                 :: "r"(addr), "r"(bytes) : "memory")
#define MBAR_WAIT(addr, parity) do {                                              \
    unsigned _m = (addr); unsigned _p = (parity); unsigned _done;                 \
    asm volatile("{\n\t.reg .pred p;\n\t"                                         \
        "mbarrier.try_wait.parity.acquire.cta.shared::cta.b64 p, [%1], %2;\n\t"   \
        "selp.b32 %0, 1, 0, p;\n\t}"                                              \
        : "=r"(_done) : "r"(_m), "r"(_p) : "memory");                             \
    if (!_done) {                                                                 \
        asm volatile("{\n\t.reg .pred P1;\n\t"                                    \
            "W1_%=:\n\t"                                                          \
            "mbarrier.try_wait.parity.acquire.cta.shared::cta.b64 P1, [%0], %1, 0x989680;\n\t" \
            "@P1 bra.uni W2_%=;\n\t"                                              \
            "bra.uni W1_%=;\n\t"                                                  \
            "W2_%=:\n\t}"                                                         \
            :: "r"(_m), "r"(_p) : "memory");                                      \
    }                                                                             \
} while (0)

// ---------------- main: 3-stage TMA ring; 1 gather serves 2 outputs ----------------
__global__ __launch_bounds__(512, 2) void main_k(float* __restrict__ out) {
    __shared__ __align__(16) uint4  s_P[NSTG][NPAIR * ROWQ];
    __shared__ __align__(16) float2 s_scx[NSTG][BT];
    __shared__ __align__(8)  unsigned long long s_bar[NSTG];

    const int o0   = blockIdx.x * OT;
    const int boff = blockIdx.y * BT;
    const int i0   = blockIdx.z * ICH;
    const int tid  = threadIdx.x;
    const int w    = tid >> 5;
    const int lane = tid & 31;
    const int ol   = lane & 7;
    const int bg   = lane >> 3;
    const int tb   = w * 32 + bg * 8;        // thread's first b within block tile

    float acc0[8], acc1[8];
    #pragma unroll
    for (int j = 0; j < 8; j++) { acc0[j] = 0.f; acc1[j] = 0.f; }

    if (tid == 0) {
        #pragma unroll
        for (int s = 0; s < NSTG; s++) MBAR_INIT(smem_u32(&s_bar[s]), 1);
    }
    __syncthreads();

    auto issue = [&](int ii, int stg) {
        const int i = i0 + ii;
        const unsigned bar = smem_u32(&s_bar[stg]);
        MBAR_EXPECT_TX(bar, TOT_BYTES);
        bulk_g2s(&s_P[stg][0],
                 g_pk + ((size_t)i * 256 + blockIdx.x * NPAIR) * ROWQ, C_BYTES, bar);
        bulk_g2s(&s_scx[stg][0], g_scx + i * BATCH + boff, SCX_BYTES, bar);
    };

    if (tid == 0) { issue(0, 0); issue(1, 1); }   // prefetch distance 2

    int cs = 0, cp = 0;        // consumer stage / phase
    int iss = 2;               // next issue stage

    for (int ii = 0; ii < ICH; ii++) {
        MBAR_WAIT(smem_u32(&s_bar[cs]), cp);

        if (tid == 0 && ii + 2 < ICH) {
            issue(ii + 2, iss);
            if (++iss == NSTG) iss = 0;
        }

        const uint4* Pc = s_P[cs];
        const uint4 qb = Pc[ol * ROWQ + 40];
        const float bw0 = __uint_as_float(qb.x);
        const float bw1 = __uint_as_float(qb.z);

        const float4* scx4 = (const float4*)&s_scx[cs][tb];
        float4 p[4];
        #pragma unroll
        for (int q = 0; q < 4; q++) p[q] = scx4[q];   // (sc,sx,sc,sx)

        #pragma unroll
        for (int j = 0; j < 8; j++) {
            const float sc = (j & 1) ? p[j >> 1].z : p[j >> 1].x;
            const float sx = (j & 1) ? p[j >> 1].w : p[j >> 1].y;
            const float sgc = fminf(fmaxf(floorf(sc), -1.f), 38.f);
            const float t  = sc - sgc - 0.5f;
            const int   m  = (int)sgc + 1;
            const uint4 q4 = Pc[ol * ROWQ + m];
            const float2 a01 = __half22float2(*(const __half2*)&q4.x);
            const float2 a23 = __half22float2(*(const __half2*)&q4.y);
            const float2 b01 = __half22float2(*(const __half2*)&q4.z);
            const float2 b23 = __half22float2(*(const __half2*)&q4.w);
            const float pa = fmaf(fmaf(fmaf(a23.y, t, a23.x), t, a01.y), t, a01.x);
            const float pb = fmaf(fmaf(fmaf(b23.y, t, b23.x), t, b01.y), t, b01.x);
            acc0[j] += fmaf(bw0, sx, pa);
            acc1[j] += fmaf(bw1, sx, pb);
        }

        __syncthreads();   // all threads done with stage cs -> it may be refilled

        if (++cs == NSTG) { cs = 0; cp ^= 1; }
    }

    #pragma unroll
    for (int j = 0; j < 8; j++) {
        const int b = boff + tb + j;
        atomicAdd(&out[b * OUT_F + o0 + ol],     acc0[j]);
        atomicAdd(&out[b * OUT_F + o0 + ol + 8], acc1[j]);
    }
}

// ---------------- launch ----------------
extern "C" void kernel_launch(void* const* d_in, const int* in_sizes, int n_in,
                              void* d_out, int out_size) {
    const float* x      = (const float*)d_in[0];  // (1024, 512)
    const float* bw     = (const float*)d_in[1];  // (512, 512)
    const float* sw     = (const float*)d_in[2];  // (512, 512, 35)
    const float* scaler = (const float*)d_in[3];  // (512, 512)
    // d_in[4] = grid (uniform; derived analytically)
    const int*   mask   = (const int*)d_in[5];    // (512, 512)
    float* out = (float*)d_out;                   // (1024, 512)

    prep_cub<<<(IN_F * OUT_F) / RB, 256>>>(sw, scaler, mask, bw);
    prep_bz<<<(IN_F * BATCH) / 256, 256>>>(x, out);
    main_k<<<dim3(OUT_F / OT, BATCH / BT, NBI), 512>>>(out);
}